// round 5
// baseline (speedup 1.0000x reference)
#include <cuda_runtime.h>

#define BB 2
#define NN 8192
#define MM 2048
#define KNN 32
#define C0 64
#define C1 128
#define C2 256
#define CIN 67            // 3 + C0
#define OUT_OFS (BB*MM*3) // new_xyz written first, then out
#define NCELL 512         // 8x8x8 morton cells

// ---------------- device scratch (no allocations allowed) ----------------
__device__ float g_xT[BB*NN*C0];   // x transposed: [b][n][c]
__device__ float g_W1t[CIN*C1];    // W1 transposed: [c][o]
__device__ float g_W2t[C1*C2];     // W2 transposed: [c][o]
__device__ int   g_idx[BB*MM*KNN]; // ball query result
__device__ float g_p[BB*MM*C2];    // pooled features pre-BN
__device__ float g_scale[C2];
__device__ float g_shift[C2];

// ---------------- packed f32x2 helpers (bit-exact per-lane rn) ----------------
__device__ __forceinline__ unsigned long long pk2(float lo, float hi) {
    unsigned long long r;
    asm("mov.b64 %0, {%1, %2};" : "=l"(r) : "f"(lo), "f"(hi));
    return r;
}
__device__ __forceinline__ void upk2(unsigned long long v, float& lo, float& hi) {
    asm("mov.b64 {%0, %1}, %2;" : "=f"(lo), "=f"(hi) : "l"(v));
}
__device__ __forceinline__ unsigned long long addx2(unsigned long long a, unsigned long long b) {
    unsigned long long r;
    asm("add.rn.f32x2 %0, %1, %2;" : "=l"(r) : "l"(a), "l"(b));
    return r;
}
__device__ __forceinline__ unsigned long long mulx2(unsigned long long a, unsigned long long b) {
    unsigned long long r;
    asm("mul.rn.f32x2 %0, %1, %2;" : "=l"(r) : "l"(a), "l"(b));
    return r;
}

__device__ __forceinline__ int cell_of(float x, float y, float z) {
    int ix = min(7, (int)(x * 8.0f));
    int iy = min(7, (int)(y * 8.0f));
    int iz = min(7, (int)(z * 8.0f));
    int c = 0;
    #pragma unroll
    for (int b = 0; b < 3; b++) {
        c |= ((ix >> b) & 1) << (3*b + 2);
        c |= ((iy >> b) & 1) << (3*b + 1);
        c |= ((iz >> b) & 1) << (3*b + 0);
    }
    return c;
}

// ---------------- FPS (blocks 0..1) + prep transposes (blocks 2..65) ----------------
// Morton-sorted points; coords held in packed f32x2 REGISTERS; warp-level
// bbox prune with 1e-4 relative margin (provably no dd change -> bit-exact
// selection). Register budget kept < 64 for the 1024-thread cap: no thread
// bbox, combos rebuilt from smem only on the compute path.
__global__ void __launch_bounds__(1024, 1)
fps_kernel(const float* __restrict__ xyz, float* __restrict__ out,
           const float* __restrict__ x,
           const float* __restrict__ W1, const float* __restrict__ W2) {
    if (blockIdx.x >= BB) {
        const int T0 = BB*C0*NN;
        const int T1 = T0 + C1*CIN;
        const int T2 = T1 + C2*C1;
        int pid = blockIdx.x - BB;
        int stride = (gridDim.x - BB) * 1024;
        for (int e = pid*1024 + threadIdx.x; e < T2; e += stride) {
            if (e < T0) {
                int n = e % NN; int bc = e / NN; int c = bc % C0; int b = bc / C0;
                g_xT[(b*NN + n)*C0 + c] = x[e];
            } else if (e < T1) {
                int f = e - T0; int c = f % CIN; int o = f / CIN;
                g_W1t[c*C1 + o] = W1[f];
            } else {
                int f = e - T1; int c = f % C1; int o = f / C1;
                g_W2t[c*C2 + o] = W2[f];
            }
        }
        return;
    }

    extern __shared__ float sm[];
    float* sxs = sm;
    float* sys = sm + NN;
    float* szs = sm + 2*NN;
    int*  sorig = (int*)(sm + 3*NN);
    int*  hist  = sorig + NN;
    unsigned* rv = (unsigned*)(hist + NCELL);
    int*  ri    = (int*)(rv + 64);
    int*  scur  = ri + 64;

    int b = blockIdx.x;
    int tid = threadIdx.x;
    int lane = tid & 31, wid = tid >> 5;
    const float* base = xyz + b*NN*3;

    // ---- counting sort by morton cell ----
    if (tid < NCELL) hist[tid] = 0;
    __syncthreads();
    for (int i = tid; i < NN; i += 1024) {
        float px = base[i*3+0], py = base[i*3+1], pz = base[i*3+2];
        atomicAdd(&hist[cell_of(px, py, pz)], 1);
    }
    __syncthreads();
    if (tid < 32) {
        int bs = tid*16;
        int loc[16]; int s = 0;
        #pragma unroll
        for (int k = 0; k < 16; k++) { loc[k] = hist[bs+k]; s += loc[k]; }
        int excl = s;
        #pragma unroll
        for (int off = 1; off < 32; off <<= 1) {
            int v = __shfl_up_sync(0xffffffffu, excl, off);
            if (lane >= off) excl += v;
        }
        excl -= s;
        int run = excl;
        #pragma unroll
        for (int k = 0; k < 16; k++) { hist[bs+k] = run; run += loc[k]; }
    }
    __syncthreads();
    for (int i = tid; i < NN; i += 1024) {
        float px = base[i*3+0], py = base[i*3+1], pz = base[i*3+2];
        int c = cell_of(px, py, pz);
        int pos = atomicAdd(&hist[c], 1);
        sxs[pos] = px; sys[pos] = py; szs[pos] = pz; sorig[pos] = i;
    }
    __syncthreads();

    // ---- setup: packed register coords, dd, warp bbox ----
    int i0 = tid * 8;
    unsigned long long pxp[4], pyp[4], pzp[4];
    float dd[8];
    float wlx, whx, wly, why_, wlz, whz;
    {
        float blx =  1e30f, bhx = -1e30f, bly =  1e30f, bhy = -1e30f;
        float blz =  1e30f, bhz = -1e30f;
        #pragma unroll
        for (int j = 0; j < 8; j++) {
            float px = sxs[i0+j], py = sys[i0+j], pz = szs[i0+j];
            blx = fminf(blx, px); bhx = fmaxf(bhx, px);
            bly = fminf(bly, py); bhy = fmaxf(bhy, py);
            blz = fminf(blz, pz); bhz = fmaxf(bhz, pz);
            dd[j] = 1e10f;
            if (sorig[i0+j] == 0) *scur = i0 + j;
        }
        #pragma unroll
        for (int q = 0; q < 4; q++) {
            pxp[q] = pk2(sxs[i0+2*q], sxs[i0+2*q+1]);
            pyp[q] = pk2(sys[i0+2*q], sys[i0+2*q+1]);
            pzp[q] = pk2(szs[i0+2*q], szs[i0+2*q+1]);
        }
        wlx = blx; whx = bhx; wly = bly; why_ = bhy; wlz = blz; whz = bhz;
        #pragma unroll
        for (int off = 16; off > 0; off >>= 1) {
            wlx = fminf(wlx, __shfl_xor_sync(0xffffffffu, wlx, off));
            whx = fmaxf(whx, __shfl_xor_sync(0xffffffffu, whx, off));
            wly = fminf(wly, __shfl_xor_sync(0xffffffffu, wly, off));
            why_ = fmaxf(why_, __shfl_xor_sync(0xffffffffu, why_, off));
            wlz = fminf(wlz, __shfl_xor_sync(0xffffffffu, wlz, off));
            whz = fmaxf(whz, __shfl_xor_sync(0xffffffffu, whz, off));
        }
    }
    unsigned gw = __float_as_uint(1e10f);
    int cw = 0;
    float wthresh = 1.0001e10f;

    __syncthreads();
    int cur = *scur;

    float* outb = out + b*MM*3;
    for (int m = 0; m < MM; m++) {
        if (tid == 0) {
            outb[m*3+0] = sxs[cur];
            outb[m*3+1] = sys[cur];
            outb[m*3+2] = szs[cur];
        }
        if (m == MM-1) break;
        float lx = sxs[cur], ly = sys[cur], lz = szs[cur];
        int buf = m & 1;

        float wdx = fmaxf(fmaxf(wlx - lx, lx - whx), 0.f);
        float wdy = fmaxf(fmaxf(wly - ly, ly - why_), 0.f);
        float wdz = fmaxf(fmaxf(wlz - lz, lz - whz), 0.f);
        float wlb2 = fmaf(wdx, wdx, fmaf(wdy, wdy, wdz*wdz));
        if (wlb2 <= wthresh) {
            unsigned long long cX = pk2(-lx, -lx);
            unsigned long long cY = pk2(-ly, -ly);
            unsigned long long cZ = pk2(-lz, -lz);
            #pragma unroll
            for (int q = 0; q < 4; q++) {
                unsigned long long dx = addx2(pxp[q], cX);
                unsigned long long dy = addx2(pyp[q], cY);
                unsigned long long dz = addx2(pzp[q], cZ);
                unsigned long long d2 = addx2(addx2(mulx2(dx,dx), mulx2(dy,dy)), mulx2(dz,dz));
                float a, c;
                upk2(d2, a, c);
                dd[2*q]   = fminf(dd[2*q],   a);
                dd[2*q+1] = fminf(dd[2*q+1], c);
            }
            // exact (value desc, (orig<<13|pos) asc) chunk argmax
            float maxv = -1.f; int maxcombo = 0x7FFFFFFF;
            #pragma unroll
            for (int j = 0; j < 8; j++) {
                int cmb = (sorig[i0+j] << 13) | (i0 + j);
                bool take = (dd[j] > maxv) || (dd[j] == maxv && cmb < maxcombo);
                if (take) { maxv = dd[j]; maxcombo = cmb; }
            }
            unsigned v = __float_as_uint(maxv);
            unsigned g = __reduce_max_sync(0xffffffffu, v);
            unsigned c = __reduce_min_sync(0xffffffffu,
                           (v == g) ? (unsigned)maxcombo : 0x7FFFFFFFu);
            gw = g; cw = (int)c;
            wthresh = __uint_as_float(g) * 1.0001f;
        }
        if (lane == 0) { rv[buf*32 + wid] = gw; ri[buf*32 + wid] = cw; }
        __syncthreads();

        unsigned pv = rv[buf*32 + lane];
        int      pi = ri[buf*32 + lane];
        unsigned g2 = __reduce_max_sync(0xffffffffu, pv);
        unsigned c2 = __reduce_min_sync(0xffffffffu,
                        (pv == g2) ? (unsigned)pi : 0x7FFFFFFFu);
        cur = (int)(c2 & 0x1FFFu);
    }
}

// ---------------- Ball query: one warp per center, in-order first-K ----------------
__global__ void __launch_bounds__(256)
ball_kernel(const float* __restrict__ xyz, const float* __restrict__ newxyz) {
    extern __shared__ float sm[];
    float* sx = sm; float* sy = sm + NN; float* sz = sm + 2*NN;
    int blkb = blockIdx.x >> 5;
    int blkc = blockIdx.x & 31;
    int tid = threadIdx.x;
    const float* base = xyz + blkb*NN*3;
    for (int i = tid; i < NN; i += 256) {
        sx[i] = base[i*3+0]; sy[i] = base[i*3+1]; sz[i] = base[i*3+2];
    }
    __syncthreads();
    int w = tid >> 5, lane = tid & 31;
    for (int s = 0; s < 8; s++) {
        int mi = blkc*64 + s*8 + w;
        int bm = blkb*MM + mi;
        float cx = newxyz[bm*3+0], cy = newxyz[bm*3+1], cz = newxyz[bm*3+2];
        int* ob = g_idx + bm*KNN;
        int cnt = 0; int first = -1;
        for (int c = 0; c < NN/32; c++) {
            int i = c*32 + lane;
            float dx = sx[i]-cx, dy = sy[i]-cy, dz = sz[i]-cz;
            float d2 = __fadd_rn(__fadd_rn(__fmul_rn(dx,dx), __fmul_rn(dy,dy)),
                                 __fmul_rn(dz,dz));
            bool in = d2 < 0.01f;
            unsigned msk = __ballot_sync(0xffffffffu, in);
            if (first < 0 && msk) first = c*32 + (__ffs(msk) - 1);
            if (in) {
                int slot = cnt + __popc(msk & ((1u << lane) - 1u));
                if (slot < KNN) ob[slot] = i;
            }
            cnt += __popc(msk);
            if (cnt >= KNN) break;
        }
        for (int s2 = cnt + lane; s2 < KNN; s2 += 32) ob[s2] = first;
    }
}

// ---------------- Group + 2-layer MLP + max-pool: one block per (b,m) ----------------
__global__ void __launch_bounds__(256, 4)
group_mlp_kernel(const float* __restrict__ xyz,
                 const float* __restrict__ b1,
                 const float* __restrict__ b2,
                 const float* __restrict__ newxyz) {
    __shared__ float gT[CIN][KNN];
    __shared__ float hS[C1][KNN];
    __shared__ int   sid[KNN];
    __shared__ float sctr[3];
    int bm = blockIdx.x;
    int b  = bm >> 11;
    int t  = threadIdx.x;

    if (t < KNN) sid[t] = g_idx[bm*KNN + t];
    if (t >= 32 && t < 35) sctr[t-32] = newxyz[bm*3 + (t-32)];
    __syncthreads();

    for (int e = t; e < CIN*KNN; e += 256) {
        int c = e >> 5, k = e & 31;
        int id = sid[k];
        float v;
        if (c < 3) v = xyz[(b*NN + id)*3 + c] - sctr[c];
        else       v = g_xT[(b*NN + id)*C0 + (c - 3)];
        gT[c][k] = v;
    }
    __syncthreads();

    {
        int o = t >> 1, kh = t & 1, ko = kh * 16;
        float acc[16];
        float bb = b1[o];
        #pragma unroll
        for (int q = 0; q < 16; q++) acc[q] = bb;
        for (int c = 0; c < CIN; c++) {
            float w = g_W1t[c*C1 + o];
            const float4* gp = (const float4*)&gT[c][ko];
            #pragma unroll
            for (int q = 0; q < 4; q++) {
                float4 gv = gp[q];
                acc[q*4+0] = fmaf(w, gv.x, acc[q*4+0]);
                acc[q*4+1] = fmaf(w, gv.y, acc[q*4+1]);
                acc[q*4+2] = fmaf(w, gv.z, acc[q*4+2]);
                acc[q*4+3] = fmaf(w, gv.w, acc[q*4+3]);
            }
        }
        float4* hp = (float4*)&hS[o][ko];
        #pragma unroll
        for (int q = 0; q < 4; q++)
            hp[q] = make_float4(fmaxf(acc[q*4+0], 0.f), fmaxf(acc[q*4+1], 0.f),
                                fmaxf(acc[q*4+2], 0.f), fmaxf(acc[q*4+3], 0.f));
    }
    __syncthreads();

    {
        float a2[32];
        #pragma unroll
        for (int k = 0; k < 32; k++) a2[k] = 0.f;
        #pragma unroll 4
        for (int c = 0; c < C1; c++) {
            float w = g_W2t[c*C2 + t];
            const float4* hp = (const float4*)&hS[c][0];
            #pragma unroll
            for (int q = 0; q < 8; q++) {
                float4 hv = hp[q];
                a2[q*4+0] = fmaf(w, hv.x, a2[q*4+0]);
                a2[q*4+1] = fmaf(w, hv.y, a2[q*4+1]);
                a2[q*4+2] = fmaf(w, hv.z, a2[q*4+2]);
                a2[q*4+3] = fmaf(w, hv.w, a2[q*4+3]);
            }
        }
        float pm = a2[0];
        #pragma unroll
        for (int k = 1; k < 32; k++) pm = fmaxf(pm, a2[k]);
        g_p[bm*C2 + t] = pm + b2[t];
    }
}

// ---------------- BN stats: one block per channel ----------------
__global__ void __launch_bounds__(256)
bn_stats_kernel(const float* __restrict__ gamma, const float* __restrict__ beta) {
    int o = blockIdx.x, t = threadIdx.x;
    float s = 0.f, s2 = 0.f;
    for (int i = t; i < BB*MM; i += 256) {
        float v = g_p[i*C2 + o];
        s += v; s2 = fmaf(v, v, s2);
    }
    __shared__ float ss[32], ssq[32];
    #pragma unroll
    for (int off = 16; off > 0; off >>= 1) {
        s  += __shfl_down_sync(0xffffffffu, s, off);
        s2 += __shfl_down_sync(0xffffffffu, s2, off);
    }
    if ((t & 31) == 0) { ss[t>>5] = s; ssq[t>>5] = s2; }
    __syncthreads();
    if (t < 32) {
        float a  = (t < 8) ? ss[t]  : 0.f;
        float aq = (t < 8) ? ssq[t] : 0.f;
        #pragma unroll
        for (int off = 4; off > 0; off >>= 1) {
            a  += __shfl_down_sync(0xffffffffu, a, off);
            aq += __shfl_down_sync(0xffffffffu, aq, off);
        }
        if (t == 0) {
            const float inv_n = 1.0f / (BB*MM);
            float mean = a * inv_n;
            float var  = fmaxf(aq * inv_n - mean*mean, 0.f);
            float rstd = rsqrtf(var + 1e-5f);
            float sc = rstd * gamma[o];
            g_scale[o] = sc;
            g_shift[o] = beta[o] - mean * sc;
        }
    }
}

// ---------------- normalize + transpose to (B, C2, M) ----------------
__global__ void __launch_bounds__(256)
norm_kernel(float* __restrict__ out) {
    int b = blockIdx.x >> 8, o = blockIdx.x & 255, t = threadIdx.x;
    float sc = g_scale[o], sh = g_shift[o];
    float* ob = out + OUT_OFS + (b*C2 + o)*MM;
    const float* pb = g_p + b*MM*C2 + o;
    for (int mm = t; mm < MM; mm += 256)
        ob[mm] = fmaf(pb[mm*C2], sc, sh);
}

// ---------------- launch ----------------
extern "C" void kernel_launch(void* const* d_in, const int* in_sizes, int n_in,
                              void* d_out, int out_size) {
    const float* xyz   = (const float*)d_in[0];
    const float* x     = (const float*)d_in[1];
    const float* W1    = (const float*)d_in[2];
    const float* b1    = (const float*)d_in[3];
    const float* W2    = (const float*)d_in[4];
    const float* b2    = (const float*)d_in[5];
    const float* gamma = (const float*)d_in[6];
    const float* beta  = (const float*)d_in[7];
    float* out = (float*)d_out;

    size_t fps_smem  = (size_t)(3*NN + NN + NCELL + 64 + 64 + 4) * 4;
    size_t ball_smem = (size_t)(3*NN)*4;
    cudaFuncSetAttribute(fps_kernel,  cudaFuncAttributeMaxDynamicSharedMemorySize, (int)fps_smem);
    cudaFuncSetAttribute(ball_kernel, cudaFuncAttributeMaxDynamicSharedMemorySize, (int)ball_smem);

    fps_kernel<<<BB + 64, 1024, fps_smem>>>(xyz, out, x, W1, W2);
    ball_kernel<<<64, 256, ball_smem>>>(xyz, out);
    group_mlp_kernel<<<BB*MM, 256>>>(xyz, b1, b2, out);
    bn_stats_kernel<<<C2, 256>>>(gamma, beta);
    norm_kernel<<<BB*C2, 256>>>(out);
}

// round 6
// speedup vs baseline: 1.1400x; 1.1400x over previous
#include <cuda_runtime.h>

#define BB 2
#define NN 8192
#define MM 2048
#define KNN 32
#define C0 64
#define C1 128
#define C2 256
#define CIN 67            // 3 + C0
#define OUT_OFS (BB*MM*3) // new_xyz written first, then out
#define NCELL 512         // 8x8x8 morton cells
#define NWORK 146         // worker blocks
#define WPB   73          // workers per batch

// ---------------- device scratch (no allocations allowed) ----------------
__device__ float g_W1t[CIN*C1];    // W1 transposed: [c][o]
__device__ float g_W2t[C1*C2];     // W2 transposed: [c][o]
__device__ int   g_sel[BB*MM];     // FPS ticket: original index + 1 (0 = not ready)
__device__ float g_p[BB*MM*C2];    // pooled features pre-BN
__device__ float g_scale[C2];
__device__ float g_shift[C2];

// ---------------- packed f32x2 helpers (bit-exact per-lane rn) ----------------
__device__ __forceinline__ unsigned long long pk2(float lo, float hi) {
    unsigned long long r;
    asm("mov.b64 %0, {%1, %2};" : "=l"(r) : "f"(lo), "f"(hi));
    return r;
}
__device__ __forceinline__ void upk2(unsigned long long v, float& lo, float& hi) {
    asm("mov.b64 {%0, %1}, %2;" : "=f"(lo), "=f"(hi) : "l"(v));
}
__device__ __forceinline__ unsigned long long addx2(unsigned long long a, unsigned long long b) {
    unsigned long long r;
    asm("add.rn.f32x2 %0, %1, %2;" : "=l"(r) : "l"(a), "l"(b));
    return r;
}
__device__ __forceinline__ unsigned long long mulx2(unsigned long long a, unsigned long long b) {
    unsigned long long r;
    asm("mul.rn.f32x2 %0, %1, %2;" : "=l"(r) : "l"(a), "l"(b));
    return r;
}

__device__ __forceinline__ int cell_of(float x, float y, float z) {
    int ix = min(7, (int)(x * 8.0f));
    int iy = min(7, (int)(y * 8.0f));
    int iz = min(7, (int)(z * 8.0f));
    int c = 0;
    #pragma unroll
    for (int b = 0; b < 3; b++) {
        c |= ((ix >> b) & 1) << (3*b + 2);
        c |= ((iy >> b) & 1) << (3*b + 1);
        c |= ((iz >> b) & 1) << (3*b + 0);
    }
    return c;
}

// smem sizes (floats)
#define FPS_SMEM_FLOATS (3*NN + NN + NCELL + 64 + 64 + 4)

// ================= FUSED persistent kernel =================
// blocks 0..1  : FPS (serial furthest-point sampling per batch)
// blocks 2..147: workers consuming centers via g_sel tickets:
//                ball query (warp 0) + grouped 2-layer MLP (all 1024 thr)
__global__ void __launch_bounds__(1024, 1)
fused_kernel(const float* __restrict__ xyz, const float* __restrict__ x,
             const float* __restrict__ W1, const float* __restrict__ b1,
             const float* __restrict__ W2, const float* __restrict__ b2,
             float* __restrict__ out) {
    extern __shared__ float sm[];
    int tid = threadIdx.x;
    int lane = tid & 31, wid = tid >> 5;

    if (blockIdx.x < BB) {
        // ==================== FPS path ====================
        float* sxs = sm;
        float* sys = sm + NN;
        float* szs = sm + 2*NN;
        int*  sorig = (int*)(sm + 3*NN);
        int*  hist  = sorig + NN;
        unsigned* rv = (unsigned*)(hist + NCELL);
        int*  ri    = (int*)(rv + 64);
        int*  scur  = ri + 64;

        int b = blockIdx.x;
        const float* base = xyz + b*NN*3;

        // ---- counting sort by morton cell ----
        if (tid < NCELL) hist[tid] = 0;
        __syncthreads();
        for (int i = tid; i < NN; i += 1024) {
            float px = base[i*3+0], py = base[i*3+1], pz = base[i*3+2];
            atomicAdd(&hist[cell_of(px, py, pz)], 1);
        }
        __syncthreads();
        if (tid < 32) {
            int bs = tid*16;
            int loc[16]; int s = 0;
            #pragma unroll
            for (int k = 0; k < 16; k++) { loc[k] = hist[bs+k]; s += loc[k]; }
            int excl = s;
            #pragma unroll
            for (int off = 1; off < 32; off <<= 1) {
                int v = __shfl_up_sync(0xffffffffu, excl, off);
                if (lane >= off) excl += v;
            }
            excl -= s;
            int run = excl;
            #pragma unroll
            for (int k = 0; k < 16; k++) { hist[bs+k] = run; run += loc[k]; }
        }
        __syncthreads();
        for (int i = tid; i < NN; i += 1024) {
            float px = base[i*3+0], py = base[i*3+1], pz = base[i*3+2];
            int c = cell_of(px, py, pz);
            int pos = atomicAdd(&hist[c], 1);
            sxs[pos] = px; sys[pos] = py; szs[pos] = pz; sorig[pos] = i;
        }
        __syncthreads();

        // ---- setup ----
        int i0 = tid * 8;
        unsigned long long pxp[4], pyp[4], pzp[4];
        float dd[8];
        float wlx, whx, wly, why_, wlz, whz;
        {
            float blx =  1e30f, bhx = -1e30f, bly =  1e30f, bhy = -1e30f;
            float blz =  1e30f, bhz = -1e30f;
            #pragma unroll
            for (int j = 0; j < 8; j++) {
                float px = sxs[i0+j], py = sys[i0+j], pz = szs[i0+j];
                blx = fminf(blx, px); bhx = fmaxf(bhx, px);
                bly = fminf(bly, py); bhy = fmaxf(bhy, py);
                blz = fminf(blz, pz); bhz = fmaxf(bhz, pz);
                dd[j] = 1e10f;
                if (sorig[i0+j] == 0) *scur = i0 + j;
            }
            #pragma unroll
            for (int q = 0; q < 4; q++) {
                pxp[q] = pk2(sxs[i0+2*q], sxs[i0+2*q+1]);
                pyp[q] = pk2(sys[i0+2*q], sys[i0+2*q+1]);
                pzp[q] = pk2(szs[i0+2*q], szs[i0+2*q+1]);
            }
            wlx = blx; whx = bhx; wly = bly; why_ = bhy; wlz = blz; whz = bhz;
            #pragma unroll
            for (int off = 16; off > 0; off >>= 1) {
                wlx = fminf(wlx, __shfl_xor_sync(0xffffffffu, wlx, off));
                whx = fmaxf(whx, __shfl_xor_sync(0xffffffffu, whx, off));
                wly = fminf(wly, __shfl_xor_sync(0xffffffffu, wly, off));
                why_ = fmaxf(why_, __shfl_xor_sync(0xffffffffu, why_, off));
                wlz = fminf(wlz, __shfl_xor_sync(0xffffffffu, wlz, off));
                whz = fmaxf(whz, __shfl_xor_sync(0xffffffffu, whz, off));
            }
        }
        unsigned gw = __float_as_uint(1e10f);
        int cw = 0;
        float wthresh = 1.0001e10f;

        __syncthreads();
        int cur = *scur;

        float* outb = out + b*MM*3;
        for (int m = 0; m < MM; m++) {
            if (tid == 0) {
                outb[m*3+0] = sxs[cur];
                outb[m*3+1] = sys[cur];
                outb[m*3+2] = szs[cur];
                ((volatile int*)g_sel)[b*MM + m] = sorig[cur] + 1;  // publish ticket
            }
            if (m == MM-1) break;
            float lx = sxs[cur], ly = sys[cur], lz = szs[cur];
            int buf = m & 1;

            float wdx = fmaxf(fmaxf(wlx - lx, lx - whx), 0.f);
            float wdy = fmaxf(fmaxf(wly - ly, ly - why_), 0.f);
            float wdz = fmaxf(fmaxf(wlz - lz, lz - whz), 0.f);
            float wlb2 = fmaf(wdx, wdx, fmaf(wdy, wdy, wdz*wdz));
            if (wlb2 <= wthresh) {
                unsigned long long cX = pk2(-lx, -lx);
                unsigned long long cY = pk2(-ly, -ly);
                unsigned long long cZ = pk2(-lz, -lz);
                #pragma unroll
                for (int q = 0; q < 4; q++) {
                    unsigned long long dx = addx2(pxp[q], cX);
                    unsigned long long dy = addx2(pyp[q], cY);
                    unsigned long long dz = addx2(pzp[q], cZ);
                    unsigned long long d2 = addx2(addx2(mulx2(dx,dx), mulx2(dy,dy)), mulx2(dz,dz));
                    float a, c;
                    upk2(d2, a, c);
                    dd[2*q]   = fminf(dd[2*q],   a);
                    dd[2*q+1] = fminf(dd[2*q+1], c);
                }
                float maxv = -1.f; int maxcombo = 0x7FFFFFFF;
                #pragma unroll
                for (int j = 0; j < 8; j++) {
                    int cmb = (sorig[i0+j] << 13) | (i0 + j);
                    bool take = (dd[j] > maxv) || (dd[j] == maxv && cmb < maxcombo);
                    if (take) { maxv = dd[j]; maxcombo = cmb; }
                }
                unsigned v = __float_as_uint(maxv);
                unsigned g = __reduce_max_sync(0xffffffffu, v);
                unsigned c = __reduce_min_sync(0xffffffffu,
                               (v == g) ? (unsigned)maxcombo : 0x7FFFFFFFu);
                gw = g; cw = (int)c;
                wthresh = __uint_as_float(g) * 1.0001f;
            }
            if (lane == 0) { rv[buf*32 + wid] = gw; ri[buf*32 + wid] = cw; }
            __syncthreads();

            unsigned pv = rv[buf*32 + lane];
            int      pi = ri[buf*32 + lane];
            unsigned g2 = __reduce_max_sync(0xffffffffu, pv);
            unsigned c2 = __reduce_min_sync(0xffffffffu,
                            (pv == g2) ? (unsigned)pi : 0x7FFFFFFFu);
            cur = (int)(c2 & 0x1FFFu);
        }
        return;
    }

    // ==================== worker path ====================
    int w = blockIdx.x - BB;       // 0..145
    int b = w & 1;
    int ws = w >> 1;               // 0..72

    float* sx = sm;
    float* sy = sm + NN;
    float* sz = sm + 2*NN;
    float* gT = sm + 3*NN;                 // [CIN][KNN]
    float* hS = gT + CIN*KNN;              // [C1][KNN]
    int*   sid = (int*)(hS + C1*KNN);      // [KNN]
    int*   soi = sid + KNN;

    // load this batch's xyz into smem
    const float* base = xyz + b*NN*3;
    for (int i = tid; i < NN; i += 1024) {
        sx[i] = base[i*3+0]; sy[i] = base[i*3+1]; sz[i] = base[i*3+2];
    }
    // redundant weight transposes (identical concurrent writes are benign;
    // visible block-wide after __syncthreads)
    for (int e = tid; e < C1*CIN; e += 1024)
        g_W1t[(e % CIN)*C1 + (e / CIN)] = W1[e];
    for (int e = tid; e < C2*C1; e += 1024)
        g_W2t[(e % C1)*C2 + (e / C1)] = W2[e];
    __syncthreads();

    for (int m = ws; m < MM; m += WPB) {
        // ---- wait for ticket ----
        if (tid == 0) {
            int v;
            while ((v = ((volatile int*)g_sel)[b*MM + m]) == 0) __nanosleep(64);
            *soi = v - 1;
        }
        __syncthreads();
        int oi = *soi;
        float cx = sx[oi], cy = sy[oi], cz = sz[oi];

        // ---- ball query: warp 0, first-K in index order ----
        if (tid < 32) {
            int cnt = 0; int first = -1;
            for (int c = 0; c < NN/32; c++) {
                int i = c*32 + lane;
                float dx = sx[i]-cx, dy = sy[i]-cy, dz = sz[i]-cz;
                float d2 = __fadd_rn(__fadd_rn(__fmul_rn(dx,dx), __fmul_rn(dy,dy)),
                                     __fmul_rn(dz,dz));
                bool in = d2 < 0.01f;
                unsigned msk = __ballot_sync(0xffffffffu, in);
                if (first < 0 && msk) first = c*32 + (__ffs(msk) - 1);
                if (in) {
                    int slot = cnt + __popc(msk & ((1u << lane) - 1u));
                    if (slot < KNN) sid[slot] = i;
                }
                cnt += __popc(msk);
                if (cnt >= KNN) break;
            }
            for (int s2 = cnt + lane; s2 < KNN; s2 += 32) sid[s2] = first;
        }
        __syncthreads();

        // ---- gather group matrix gT[c][k] ----
        for (int e = tid; e < CIN*KNN; e += 1024) {
            int c = e >> 5, k = e & 31;
            int id = sid[k];
            float v;
            if      (c == 0) v = sx[id] - cx;
            else if (c == 1) v = sy[id] - cy;
            else if (c == 2) v = sz[id] - cz;
            else             v = x[(b*C0 + (c - 3))*NN + id];
            gT[c*KNN + k] = v;
        }
        __syncthreads();

        // ---- layer 1: thread = (o in [0,128), quarter of k) ----
        {
            int o = tid >> 3, k0 = (tid & 7) * 4;
            float acc0 = b1[o], acc1 = acc0, acc2 = acc0, acc3 = acc0;
            for (int c = 0; c < CIN; c++) {
                float wv = g_W1t[c*C1 + o];
                float4 gv = *(const float4*)&gT[c*KNN + k0];
                acc0 = fmaf(wv, gv.x, acc0);
                acc1 = fmaf(wv, gv.y, acc1);
                acc2 = fmaf(wv, gv.z, acc2);
                acc3 = fmaf(wv, gv.w, acc3);
            }
            *(float4*)&hS[o*KNN + k0] =
                make_float4(fmaxf(acc0, 0.f), fmaxf(acc1, 0.f),
                            fmaxf(acc2, 0.f), fmaxf(acc3, 0.f));
        }
        __syncthreads();

        // ---- layer 2: thread = (o in [0,256), eighth of k) + warp max ----
        {
            int o = tid >> 2, g = tid & 3, k0 = g * 8;
            float a0=0.f,a1=0.f,a2=0.f,a3=0.f,a4=0.f,a5=0.f,a6=0.f,a7=0.f;
            #pragma unroll 4
            for (int c = 0; c < C1; c++) {
                float wv = g_W2t[c*C2 + o];
                float4 h0 = *(const float4*)&hS[c*KNN + k0];
                float4 h1 = *(const float4*)&hS[c*KNN + k0 + 4];
                a0 = fmaf(wv, h0.x, a0); a1 = fmaf(wv, h0.y, a1);
                a2 = fmaf(wv, h0.z, a2); a3 = fmaf(wv, h0.w, a3);
                a4 = fmaf(wv, h1.x, a4); a5 = fmaf(wv, h1.y, a5);
                a6 = fmaf(wv, h1.z, a6); a7 = fmaf(wv, h1.w, a7);
            }
            float pm = fmaxf(fmaxf(fmaxf(a0,a1), fmaxf(a2,a3)),
                             fmaxf(fmaxf(a4,a5), fmaxf(a6,a7)));
            pm = fmaxf(pm, __shfl_xor_sync(0xffffffffu, pm, 1));
            pm = fmaxf(pm, __shfl_xor_sync(0xffffffffu, pm, 2));
            if (g == 0) g_p[(b*MM + m)*C2 + o] = pm + b2[o];
        }
        __syncthreads();
    }
}

// ---------------- BN stats: one block per channel ----------------
__global__ void __launch_bounds__(256)
bn_stats_kernel(const float* __restrict__ gamma, const float* __restrict__ beta) {
    int o = blockIdx.x, t = threadIdx.x;
    float s = 0.f, s2 = 0.f;
    for (int i = t; i < BB*MM; i += 256) {
        float v = g_p[i*C2 + o];
        s += v; s2 = fmaf(v, v, s2);
    }
    __shared__ float ss[32], ssq[32];
    #pragma unroll
    for (int off = 16; off > 0; off >>= 1) {
        s  += __shfl_down_sync(0xffffffffu, s, off);
        s2 += __shfl_down_sync(0xffffffffu, s2, off);
    }
    if ((t & 31) == 0) { ss[t>>5] = s; ssq[t>>5] = s2; }
    __syncthreads();
    if (t < 32) {
        float a  = (t < 8) ? ss[t]  : 0.f;
        float aq = (t < 8) ? ssq[t] : 0.f;
        #pragma unroll
        for (int off = 4; off > 0; off >>= 1) {
            a  += __shfl_down_sync(0xffffffffu, a, off);
            aq += __shfl_down_sync(0xffffffffu, aq, off);
        }
        if (t == 0) {
            const float inv_n = 1.0f / (BB*MM);
            float mean = a * inv_n;
            float var  = fmaxf(aq * inv_n - mean*mean, 0.f);
            float rstd = rsqrtf(var + 1e-5f);
            float sc = rstd * gamma[o];
            g_scale[o] = sc;
            g_shift[o] = beta[o] - mean * sc;
        }
    }
}

// ---------------- normalize + transpose to (B, C2, M) ----------------
__global__ void __launch_bounds__(256)
norm_kernel(float* __restrict__ out) {
    int b = blockIdx.x >> 8, o = blockIdx.x & 255, t = threadIdx.x;
    float sc = g_scale[o], sh = g_shift[o];
    float* ob = out + OUT_OFS + (b*C2 + o)*MM;
    const float* pb = g_p + b*MM*C2 + o;
    for (int mm = t; mm < MM; mm += 256)
        ob[mm] = fmaf(pb[mm*C2], sc, sh);
}

// ---------------- launch ----------------
extern "C" void kernel_launch(void* const* d_in, const int* in_sizes, int n_in,
                              void* d_out, int out_size) {
    const float* xyz   = (const float*)d_in[0];
    const float* x     = (const float*)d_in[1];
    const float* W1    = (const float*)d_in[2];
    const float* b1    = (const float*)d_in[3];
    const float* W2    = (const float*)d_in[4];
    const float* b2    = (const float*)d_in[5];
    const float* gamma = (const float*)d_in[6];
    const float* beta  = (const float*)d_in[7];
    float* out = (float*)d_out;

    size_t smem = (size_t)FPS_SMEM_FLOATS * 4;   // 133,648 B (covers worker layout too)
    cudaFuncSetAttribute(fused_kernel, cudaFuncAttributeMaxDynamicSharedMemorySize, (int)smem);

    fused_kernel<<<BB + NWORK, 1024, smem>>>(xyz, x, W1, b1, W2, b2, out);
    bn_stats_kernel<<<C2, 256>>>(gamma, beta);
    norm_kernel<<<BB*C2, 256>>>(out);
}

// round 7
// speedup vs baseline: 1.3424x; 1.1776x over previous
#include <cuda_runtime.h>

#define BB 2
#define NN 8192
#define MM 2048
#define KNN 32
#define C0 64
#define C1 128
#define C2 256
#define CIN 67            // 3 + C0
#define OUT_OFS (BB*MM*3) // new_xyz written first, then out
#define NCELL 512         // 8x8x8 morton cells
#define NWORK 146         // worker blocks
#define WPB   73          // workers per batch
#define NT    512         // threads per block
#define NWARP 16          // FPS warps
#define PPT   16          // points per FPS thread

// ---------------- device scratch (no allocations allowed) ----------------
__device__ float g_W1t[CIN*C1];    // W1 transposed: [c][o]
__device__ float g_W2t[C1*C2];     // W2 transposed: [c][o]
__device__ int   g_sel[BB*MM];     // FPS ticket: original index + 1 (0 = not ready)
__device__ float g_p[BB*MM*C2];    // pooled features pre-BN
__device__ float g_scale[C2];
__device__ float g_shift[C2];

// ---------------- packed f32x2 helpers (bit-exact per-lane rn) ----------------
__device__ __forceinline__ unsigned long long pk2(float lo, float hi) {
    unsigned long long r;
    asm("mov.b64 %0, {%1, %2};" : "=l"(r) : "f"(lo), "f"(hi));
    return r;
}
__device__ __forceinline__ void upk2(unsigned long long v, float& lo, float& hi) {
    asm("mov.b64 {%0, %1}, %2;" : "=f"(lo), "=f"(hi) : "l"(v));
}
__device__ __forceinline__ unsigned long long addx2(unsigned long long a, unsigned long long b) {
    unsigned long long r;
    asm("add.rn.f32x2 %0, %1, %2;" : "=l"(r) : "l"(a), "l"(b));
    return r;
}
__device__ __forceinline__ unsigned long long mulx2(unsigned long long a, unsigned long long b) {
    unsigned long long r;
    asm("mul.rn.f32x2 %0, %1, %2;" : "=l"(r) : "l"(a), "l"(b));
    return r;
}

__device__ __forceinline__ int cell_of(float x, float y, float z) {
    int ix = min(7, (int)(x * 8.0f));
    int iy = min(7, (int)(y * 8.0f));
    int iz = min(7, (int)(z * 8.0f));
    int c = 0;
    #pragma unroll
    for (int b = 0; b < 3; b++) {
        c |= ((ix >> b) & 1) << (3*b + 2);
        c |= ((iy >> b) & 1) << (3*b + 1);
        c |= ((iz >> b) & 1) << (3*b + 0);
    }
    return c;
}

// smem size (floats): max of FPS and worker layouts
#define FPS_SMEM_FLOATS (3*NN + NN + NCELL + 32 + 32 + 4)

// ================= FUSED persistent kernel =================
__global__ void __launch_bounds__(NT, 1)
fused_kernel(const float* __restrict__ xyz, const float* __restrict__ x,
             const float* __restrict__ W1, const float* __restrict__ b1,
             const float* __restrict__ W2, const float* __restrict__ b2,
             float* __restrict__ out) {
    extern __shared__ float sm[];
    int tid = threadIdx.x;
    int lane = tid & 31, wid = tid >> 5;

    if (blockIdx.x < BB) {
        // ==================== FPS path: 16 warps, 16 pts/thread ====================
        float* sxs = sm;
        float* sys = sm + NN;
        float* szs = sm + 2*NN;
        int*  sorig = (int*)(sm + 3*NN);
        int*  hist  = sorig + NN;
        unsigned* rv = (unsigned*)(hist + NCELL);  // [2][16]
        int*  ri    = (int*)(rv + 32);             // [2][16]
        int*  scur  = ri + 32;

        int b = blockIdx.x;
        const float* base = xyz + b*NN*3;

        // ---- counting sort by morton cell ----
        if (tid < NCELL) hist[tid] = 0;
        __syncthreads();
        for (int i = tid; i < NN; i += NT) {
            float px = base[i*3+0], py = base[i*3+1], pz = base[i*3+2];
            atomicAdd(&hist[cell_of(px, py, pz)], 1);
        }
        __syncthreads();
        if (tid < 32) {
            int bs = tid*16;
            int loc[16]; int s = 0;
            #pragma unroll
            for (int k = 0; k < 16; k++) { loc[k] = hist[bs+k]; s += loc[k]; }
            int excl = s;
            #pragma unroll
            for (int off = 1; off < 32; off <<= 1) {
                int v = __shfl_up_sync(0xffffffffu, excl, off);
                if (lane >= off) excl += v;
            }
            excl -= s;
            int run = excl;
            #pragma unroll
            for (int k = 0; k < 16; k++) { hist[bs+k] = run; run += loc[k]; }
        }
        __syncthreads();
        for (int i = tid; i < NN; i += NT) {
            float px = base[i*3+0], py = base[i*3+1], pz = base[i*3+2];
            int c = cell_of(px, py, pz);
            int pos = atomicAdd(&hist[c], 1);
            sxs[pos] = px; sys[pos] = py; szs[pos] = pz; sorig[pos] = i;
        }
        __syncthreads();

        // ---- setup: packed register coords, dd, warp bbox ----
        int i0 = tid * PPT;
        unsigned long long pxp[PPT/2], pyp[PPT/2], pzp[PPT/2];
        float dd[PPT];
        float wlx, whx, wly, why_, wlz, whz;
        {
            float blx =  1e30f, bhx = -1e30f, bly =  1e30f, bhy = -1e30f;
            float blz =  1e30f, bhz = -1e30f;
            #pragma unroll
            for (int j = 0; j < PPT; j++) {
                float px = sxs[i0+j], py = sys[i0+j], pz = szs[i0+j];
                blx = fminf(blx, px); bhx = fmaxf(bhx, px);
                bly = fminf(bly, py); bhy = fmaxf(bhy, py);
                blz = fminf(blz, pz); bhz = fmaxf(bhz, pz);
                dd[j] = 1e10f;
                if (sorig[i0+j] == 0) *scur = i0 + j;
            }
            #pragma unroll
            for (int q = 0; q < PPT/2; q++) {
                pxp[q] = pk2(sxs[i0+2*q], sxs[i0+2*q+1]);
                pyp[q] = pk2(sys[i0+2*q], sys[i0+2*q+1]);
                pzp[q] = pk2(szs[i0+2*q], szs[i0+2*q+1]);
            }
            wlx = blx; whx = bhx; wly = bly; why_ = bhy; wlz = blz; whz = bhz;
            #pragma unroll
            for (int off = 16; off > 0; off >>= 1) {
                wlx = fminf(wlx, __shfl_xor_sync(0xffffffffu, wlx, off));
                whx = fmaxf(whx, __shfl_xor_sync(0xffffffffu, whx, off));
                wly = fminf(wly, __shfl_xor_sync(0xffffffffu, wly, off));
                why_ = fmaxf(why_, __shfl_xor_sync(0xffffffffu, why_, off));
                wlz = fminf(wlz, __shfl_xor_sync(0xffffffffu, wlz, off));
                whz = fmaxf(whz, __shfl_xor_sync(0xffffffffu, whz, off));
            }
        }
        unsigned gw = __float_as_uint(1e10f);
        int cw = 0;
        float wthresh = 1.0001e10f;

        __syncthreads();
        int cur = *scur;

        float* outb = out + b*MM*3;
        for (int m = 0; m < MM; m++) {
            if (tid == 0) {
                outb[m*3+0] = sxs[cur];
                outb[m*3+1] = sys[cur];
                outb[m*3+2] = szs[cur];
                ((volatile int*)g_sel)[b*MM + m] = sorig[cur] + 1;  // publish ticket
            }
            if (m == MM-1) break;
            float lx = sxs[cur], ly = sys[cur], lz = szs[cur];
            int buf = m & 1;

            float wdx = fmaxf(fmaxf(wlx - lx, lx - whx), 0.f);
            float wdy = fmaxf(fmaxf(wly - ly, ly - why_), 0.f);
            float wdz = fmaxf(fmaxf(wlz - lz, lz - whz), 0.f);
            float wlb2 = fmaf(wdx, wdx, fmaf(wdy, wdy, wdz*wdz));
            if (wlb2 <= wthresh) {
                unsigned long long cX = pk2(-lx, -lx);
                unsigned long long cY = pk2(-ly, -ly);
                unsigned long long cZ = pk2(-lz, -lz);
                #pragma unroll
                for (int q = 0; q < PPT/2; q++) {
                    unsigned long long dx = addx2(pxp[q], cX);
                    unsigned long long dy = addx2(pyp[q], cY);
                    unsigned long long dz = addx2(pzp[q], cZ);
                    unsigned long long d2 = addx2(addx2(mulx2(dx,dx), mulx2(dy,dy)), mulx2(dz,dz));
                    float a, c;
                    upk2(d2, a, c);
                    dd[2*q]   = fminf(dd[2*q],   a);
                    dd[2*q+1] = fminf(dd[2*q+1], c);
                }
                // exact (value desc, (orig<<13|pos) asc) chunk argmax
                float maxv = -1.f; int maxcombo = 0x7FFFFFFF;
                #pragma unroll
                for (int j = 0; j < PPT; j++) {
                    int cmb = (sorig[i0+j] << 13) | (i0 + j);
                    bool take = (dd[j] > maxv) || (dd[j] == maxv && cmb < maxcombo);
                    if (take) { maxv = dd[j]; maxcombo = cmb; }
                }
                unsigned v = __float_as_uint(maxv);
                unsigned g = __reduce_max_sync(0xffffffffu, v);
                unsigned c = __reduce_min_sync(0xffffffffu,
                               (v == g) ? (unsigned)maxcombo : 0x7FFFFFFFu);
                gw = g; cw = (int)c;
                wthresh = __uint_as_float(g) * 1.0001f;
            }
            if (lane == 0) { rv[buf*NWARP + wid] = gw; ri[buf*NWARP + wid] = cw; }
            __syncthreads();

            unsigned pv = (lane < NWARP) ? rv[buf*NWARP + lane] : 0u;
            int      pi = (lane < NWARP) ? ri[buf*NWARP + lane] : 0x7FFFFFFF;
            unsigned g2 = __reduce_max_sync(0xffffffffu, pv);
            unsigned c2 = __reduce_min_sync(0xffffffffu,
                            (pv == g2) ? (unsigned)pi : 0x7FFFFFFFu);
            cur = (int)(c2 & 0x1FFFu);
        }
        return;
    }

    // ==================== worker path (512 threads) ====================
    int w = blockIdx.x - BB;       // 0..145
    int b = w & 1;
    int ws = w >> 1;               // 0..72

    float* sx = sm;
    float* sy = sm + NN;
    float* sz = sm + 2*NN;
    float* gT = sm + 3*NN;                 // [CIN][KNN]
    float* hS = gT + CIN*KNN;              // [C1][KNN]
    int*   sid = (int*)(hS + C1*KNN);      // [KNN]
    int*   soi = sid + KNN;

    const float* base = xyz + b*NN*3;
    for (int i = tid; i < NN; i += NT) {
        sx[i] = base[i*3+0]; sy[i] = base[i*3+1]; sz[i] = base[i*3+2];
    }
    // redundant weight transposes (identical concurrent writes are benign)
    for (int e = tid; e < C1*CIN; e += NT)
        g_W1t[(e % CIN)*C1 + (e / CIN)] = W1[e];
    for (int e = tid; e < C2*C1; e += NT)
        g_W2t[(e % C1)*C2 + (e / C1)] = W2[e];
    __syncthreads();

    for (int m = ws; m < MM; m += WPB) {
        // ---- wait for ticket ----
        if (tid == 0) {
            int v;
            while ((v = ((volatile int*)g_sel)[b*MM + m]) == 0) __nanosleep(64);
            *soi = v - 1;
        }
        __syncthreads();
        int oi = *soi;
        float cx = sx[oi], cy = sy[oi], cz = sz[oi];

        // ---- ball query: warp 0, first-K in index order ----
        if (tid < 32) {
            int cnt = 0; int first = -1;
            for (int c = 0; c < NN/32; c++) {
                int i = c*32 + lane;
                float dx = sx[i]-cx, dy = sy[i]-cy, dz = sz[i]-cz;
                float d2 = __fadd_rn(__fadd_rn(__fmul_rn(dx,dx), __fmul_rn(dy,dy)),
                                     __fmul_rn(dz,dz));
                bool in = d2 < 0.01f;
                unsigned msk = __ballot_sync(0xffffffffu, in);
                if (first < 0 && msk) first = c*32 + (__ffs(msk) - 1);
                if (in) {
                    int slot = cnt + __popc(msk & ((1u << lane) - 1u));
                    if (slot < KNN) sid[slot] = i;
                }
                cnt += __popc(msk);
                if (cnt >= KNN) break;
            }
            for (int s2 = cnt + lane; s2 < KNN; s2 += 32) sid[s2] = first;
        }
        __syncthreads();

        // ---- gather group matrix gT[c][k] ----
        for (int e = tid; e < CIN*KNN; e += NT) {
            int c = e >> 5, k = e & 31;
            int id = sid[k];
            float v;
            if      (c == 0) v = sx[id] - cx;
            else if (c == 1) v = sy[id] - cy;
            else if (c == 2) v = sz[id] - cz;
            else             v = x[(b*C0 + (c - 3))*NN + id];
            gT[c*KNN + k] = v;
        }
        __syncthreads();

        // ---- layer 1: thread = (o in [0,128), quarter of k -> 8 accs) ----
        {
            int o = tid >> 2, k0 = (tid & 3) * 8;
            float a0 = b1[o], a1=a0,a2=a0,a3=a0,a4=a0,a5=a0,a6=a0,a7=a0;
            for (int c = 0; c < CIN; c++) {
                float wv = g_W1t[c*C1 + o];
                float4 g0 = *(const float4*)&gT[c*KNN + k0];
                float4 g1 = *(const float4*)&gT[c*KNN + k0 + 4];
                a0 = fmaf(wv, g0.x, a0); a1 = fmaf(wv, g0.y, a1);
                a2 = fmaf(wv, g0.z, a2); a3 = fmaf(wv, g0.w, a3);
                a4 = fmaf(wv, g1.x, a4); a5 = fmaf(wv, g1.y, a5);
                a6 = fmaf(wv, g1.z, a6); a7 = fmaf(wv, g1.w, a7);
            }
            *(float4*)&hS[o*KNN + k0] =
                make_float4(fmaxf(a0,0.f), fmaxf(a1,0.f), fmaxf(a2,0.f), fmaxf(a3,0.f));
            *(float4*)&hS[o*KNN + k0 + 4] =
                make_float4(fmaxf(a4,0.f), fmaxf(a5,0.f), fmaxf(a6,0.f), fmaxf(a7,0.f));
        }
        __syncthreads();

        // ---- layer 2: thread = (o in [0,256), half of k -> 16 accs) ----
        {
            int o = tid >> 1, g = tid & 1, k0 = g * 16;
            float acc[16];
            #pragma unroll
            for (int q = 0; q < 16; q++) acc[q] = 0.f;
            #pragma unroll 4
            for (int c = 0; c < C1; c++) {
                float wv = g_W2t[c*C2 + o];
                const float4* hp = (const float4*)&hS[c*KNN + k0];
                #pragma unroll
                for (int q = 0; q < 4; q++) {
                    float4 hv = hp[q];
                    acc[q*4+0] = fmaf(wv, hv.x, acc[q*4+0]);
                    acc[q*4+1] = fmaf(wv, hv.y, acc[q*4+1]);
                    acc[q*4+2] = fmaf(wv, hv.z, acc[q*4+2]);
                    acc[q*4+3] = fmaf(wv, hv.w, acc[q*4+3]);
                }
            }
            float pm = acc[0];
            #pragma unroll
            for (int q = 1; q < 16; q++) pm = fmaxf(pm, acc[q]);
            pm = fmaxf(pm, __shfl_xor_sync(0xffffffffu, pm, 1));
            if (g == 0) g_p[(b*MM + m)*C2 + o] = pm + b2[o];
        }
        __syncthreads();
    }
}

// ---------------- BN stats: one block per channel ----------------
__global__ void __launch_bounds__(256)
bn_stats_kernel(const float* __restrict__ gamma, const float* __restrict__ beta) {
    int o = blockIdx.x, t = threadIdx.x;
    float s = 0.f, s2 = 0.f;
    for (int i = t; i < BB*MM; i += 256) {
        float v = g_p[i*C2 + o];
        s += v; s2 = fmaf(v, v, s2);
    }
    __shared__ float ss[32], ssq[32];
    #pragma unroll
    for (int off = 16; off > 0; off >>= 1) {
        s  += __shfl_down_sync(0xffffffffu, s, off);
        s2 += __shfl_down_sync(0xffffffffu, s2, off);
    }
    if ((t & 31) == 0) { ss[t>>5] = s; ssq[t>>5] = s2; }
    __syncthreads();
    if (t < 32) {
        float a  = (t < 8) ? ss[t]  : 0.f;
        float aq = (t < 8) ? ssq[t] : 0.f;
        #pragma unroll
        for (int off = 4; off > 0; off >>= 1) {
            a  += __shfl_down_sync(0xffffffffu, a, off);
            aq += __shfl_down_sync(0xffffffffu, aq, off);
        }
        if (t == 0) {
            const float inv_n = 1.0f / (BB*MM);
            float mean = a * inv_n;
            float var  = fmaxf(aq * inv_n - mean*mean, 0.f);
            float rstd = rsqrtf(var + 1e-5f);
            float sc = rstd * gamma[o];
            g_scale[o] = sc;
            g_shift[o] = beta[o] - mean * sc;
        }
    }
}

// ---------------- normalize + transpose to (B, C2, M) ----------------
__global__ void __launch_bounds__(256)
norm_kernel(float* __restrict__ out) {
    int b = blockIdx.x >> 8, o = blockIdx.x & 255, t = threadIdx.x;
    float sc = g_scale[o], sh = g_shift[o];
    float* ob = out + OUT_OFS + (b*C2 + o)*MM;
    const float* pb = g_p + b*MM*C2 + o;
    for (int mm = t; mm < MM; mm += 256)
        ob[mm] = fmaf(pb[mm*C2], sc, sh);
}

// ---------------- launch ----------------
extern "C" void kernel_launch(void* const* d_in, const int* in_sizes, int n_in,
                              void* d_out, int out_size) {
    const float* xyz   = (const float*)d_in[0];
    const float* x     = (const float*)d_in[1];
    const float* W1    = (const float*)d_in[2];
    const float* b1    = (const float*)d_in[3];
    const float* W2    = (const float*)d_in[4];
    const float* b2    = (const float*)d_in[5];
    const float* gamma = (const float*)d_in[6];
    const float* beta  = (const float*)d_in[7];
    float* out = (float*)d_out;

    size_t smem = (size_t)FPS_SMEM_FLOATS * 4;
    cudaFuncSetAttribute(fused_kernel, cudaFuncAttributeMaxDynamicSharedMemorySize, (int)smem);

    fused_kernel<<<BB + NWORK, NT, smem>>>(xyz, x, W1, b1, W2, b2, out);
    bn_stats_kernel<<<C2, 256>>>(gamma, beta);
    norm_kernel<<<BB*C2, 256>>>(out);
}

// round 8
// speedup vs baseline: 1.3525x; 1.0075x over previous
#include <cuda_runtime.h>

#define BB 2
#define NN 8192
#define MM 2048
#define KNN 32
#define C0 64
#define C1 128
#define C2 256
#define CIN 67            // 3 + C0
#define OUT_OFS (BB*MM*3) // new_xyz written first, then out
#define NCELL 512         // 8x8x8 morton cells
#define NWORK 146         // worker blocks
#define WPB   73          // workers per batch
#define NT    512         // threads per block
#define NWARP 16          // FPS warps
#define PPT   16          // points per FPS thread

// ---------------- device scratch (no allocations allowed) ----------------
__device__ float g_W1t[CIN*C1];    // W1 transposed: [c][o]
__device__ float g_W2t[C1*C2];     // W2 transposed: [c][o]
__device__ int   g_sel[BB*MM];     // FPS ticket: original index + 1 (0 = not ready)
__device__ float g_p[BB*MM*C2];    // pooled features pre-BN
__device__ float g_scale[C2];
__device__ float g_shift[C2];

// ---------------- packed f32x2 helpers (bit-exact per-lane rn) ----------------
__device__ __forceinline__ unsigned long long pk2(float lo, float hi) {
    unsigned long long r;
    asm("mov.b64 %0, {%1, %2};" : "=l"(r) : "f"(lo), "f"(hi));
    return r;
}
__device__ __forceinline__ void upk2(unsigned long long v, float& lo, float& hi) {
    asm("mov.b64 {%0, %1}, %2;" : "=f"(lo), "=f"(hi) : "l"(v));
}
__device__ __forceinline__ unsigned long long addx2(unsigned long long a, unsigned long long b) {
    unsigned long long r;
    asm("add.rn.f32x2 %0, %1, %2;" : "=l"(r) : "l"(a), "l"(b));
    return r;
}
__device__ __forceinline__ unsigned long long mulx2(unsigned long long a, unsigned long long b) {
    unsigned long long r;
    asm("mul.rn.f32x2 %0, %1, %2;" : "=l"(r) : "l"(a), "l"(b));
    return r;
}

__device__ __forceinline__ int cell_of(float x, float y, float z) {
    int ix = min(7, (int)(x * 8.0f));
    int iy = min(7, (int)(y * 8.0f));
    int iz = min(7, (int)(z * 8.0f));
    int c = 0;
    #pragma unroll
    for (int b = 0; b < 3; b++) {
        c |= ((ix >> b) & 1) << (3*b + 2);
        c |= ((iy >> b) & 1) << (3*b + 1);
        c |= ((iz >> b) & 1) << (3*b + 0);
    }
    return c;
}

// smem size (floats): max of FPS and worker layouts
#define FPS_SMEM_FLOATS (3*NN + NN + NCELL + 32 + 8)

// ================= FUSED persistent kernel =================
__global__ void __launch_bounds__(NT, 1)
fused_kernel(const float* __restrict__ xyz, const float* __restrict__ x,
             const float* __restrict__ W1, const float* __restrict__ b1,
             const float* __restrict__ W2, const float* __restrict__ b2,
             float* __restrict__ out) {
    extern __shared__ float sm[];
    int tid = threadIdx.x;
    int lane = tid & 31, wid = tid >> 5;

    if (blockIdx.x < BB) {
        // ==================== FPS path: 16 warps, 16 pts/thread ====================
        float* sxs = sm;
        float* sys = sm + NN;
        float* szs = sm + 2*NN;
        int*  sorig = (int*)(sm + 3*NN);
        int*  hist  = sorig + NN;
        unsigned* rv = (unsigned*)(hist + NCELL);  // [2][16] warp value-bits
        int*  scombo = (int*)(rv + 32);            // [2] winner combo
        int*  scur   = scombo + 2;

        int b = blockIdx.x;
        const float* base = xyz + b*NN*3;

        // ---- counting sort by morton cell ----
        if (tid < NCELL) hist[tid] = 0;
        __syncthreads();
        for (int i = tid; i < NN; i += NT) {
            float px = base[i*3+0], py = base[i*3+1], pz = base[i*3+2];
            atomicAdd(&hist[cell_of(px, py, pz)], 1);
        }
        __syncthreads();
        if (tid < 32) {
            int bs = tid*16;
            int loc[16]; int s = 0;
            #pragma unroll
            for (int k = 0; k < 16; k++) { loc[k] = hist[bs+k]; s += loc[k]; }
            int excl = s;
            #pragma unroll
            for (int off = 1; off < 32; off <<= 1) {
                int v = __shfl_up_sync(0xffffffffu, excl, off);
                if (lane >= off) excl += v;
            }
            excl -= s;
            int run = excl;
            #pragma unroll
            for (int k = 0; k < 16; k++) { hist[bs+k] = run; run += loc[k]; }
        }
        __syncthreads();
        for (int i = tid; i < NN; i += NT) {
            float px = base[i*3+0], py = base[i*3+1], pz = base[i*3+2];
            int c = cell_of(px, py, pz);
            int pos = atomicAdd(&hist[c], 1);
            sxs[pos] = px; sys[pos] = py; szs[pos] = pz; sorig[pos] = i;
        }
        __syncthreads();

        // ---- setup: packed register coords, dd, warp bbox ----
        int i0 = tid * PPT;
        unsigned long long pxp[PPT/2], pyp[PPT/2], pzp[PPT/2];
        float dd[PPT];
        float wlx, whx, wly, why_, wlz, whz;
        {
            float blx =  1e30f, bhx = -1e30f, bly =  1e30f, bhy = -1e30f;
            float blz =  1e30f, bhz = -1e30f;
            #pragma unroll
            for (int j = 0; j < PPT; j++) {
                float px = sxs[i0+j], py = sys[i0+j], pz = szs[i0+j];
                blx = fminf(blx, px); bhx = fmaxf(bhx, px);
                bly = fminf(bly, py); bhy = fmaxf(bhy, py);
                blz = fminf(blz, pz); bhz = fmaxf(bhz, pz);
                dd[j] = 1e10f;
                if (sorig[i0+j] == 0) *scur = i0 + j;
            }
            #pragma unroll
            for (int q = 0; q < PPT/2; q++) {
                pxp[q] = pk2(sxs[i0+2*q], sxs[i0+2*q+1]);
                pyp[q] = pk2(sys[i0+2*q], sys[i0+2*q+1]);
                pzp[q] = pk2(szs[i0+2*q], szs[i0+2*q+1]);
            }
            wlx = blx; whx = bhx; wly = bly; why_ = bhy; wlz = blz; whz = bhz;
            #pragma unroll
            for (int off = 16; off > 0; off >>= 1) {
                wlx = fminf(wlx, __shfl_xor_sync(0xffffffffu, wlx, off));
                whx = fmaxf(whx, __shfl_xor_sync(0xffffffffu, whx, off));
                wly = fminf(wly, __shfl_xor_sync(0xffffffffu, wly, off));
                why_ = fmaxf(why_, __shfl_xor_sync(0xffffffffu, why_, off));
                wlz = fminf(wlz, __shfl_xor_sync(0xffffffffu, wlz, off));
                whz = fmaxf(whz, __shfl_xor_sync(0xffffffffu, whz, off));
            }
        }
        float tmax = 1e10f;                 // this thread's chunk max (always current)
        unsigned gw = __float_as_uint(1e10f);
        float wthresh = 1.0001e10f;
        if (tid == 0) { scombo[0] = 0x7FFFFFFF; scombo[1] = 0x7FFFFFFF; }

        __syncthreads();
        int cur = *scur;

        float* outb = out + b*MM*3;
        for (int m = 0; m < MM; m++) {
            if (tid == 0) {
                outb[m*3+0] = sxs[cur];
                outb[m*3+1] = sys[cur];
                outb[m*3+2] = szs[cur];
                ((volatile int*)g_sel)[b*MM + m] = sorig[cur] + 1;  // publish ticket
            }
            if (m == MM-1) break;
            float lx = sxs[cur], ly = sys[cur], lz = szs[cur];
            int buf = m & 1;

            // warp-level bbox prune (1e-4 relative margin: provably no dd change)
            float wdx = fmaxf(fmaxf(wlx - lx, lx - whx), 0.f);
            float wdy = fmaxf(fmaxf(wly - ly, ly - why_), 0.f);
            float wdz = fmaxf(fmaxf(wlz - lz, lz - whz), 0.f);
            float wlb2 = fmaf(wdx, wdx, fmaf(wdy, wdy, wdz*wdz));
            if (wlb2 <= wthresh) {
                unsigned long long cX = pk2(-lx, -lx);
                unsigned long long cY = pk2(-ly, -ly);
                unsigned long long cZ = pk2(-lz, -lz);
                #pragma unroll
                for (int q = 0; q < PPT/2; q++) {
                    unsigned long long dx = addx2(pxp[q], cX);
                    unsigned long long dy = addx2(pyp[q], cY);
                    unsigned long long dz = addx2(pzp[q], cZ);
                    unsigned long long d2 = addx2(addx2(mulx2(dx,dx), mulx2(dy,dy)), mulx2(dz,dz));
                    float a, c;
                    upk2(d2, a, c);
                    dd[2*q]   = fminf(dd[2*q],   a);
                    dd[2*q+1] = fminf(dd[2*q+1], c);
                }
                // value-only chunk max (tree)
                float m0 = fmaxf(dd[0], dd[1]),  m1 = fmaxf(dd[2], dd[3]);
                float m2 = fmaxf(dd[4], dd[5]),  m3 = fmaxf(dd[6], dd[7]);
                float m4 = fmaxf(dd[8], dd[9]),  m5 = fmaxf(dd[10], dd[11]);
                float m6 = fmaxf(dd[12], dd[13]), m7 = fmaxf(dd[14], dd[15]);
                tmax = fmaxf(fmaxf(fmaxf(m0,m1), fmaxf(m2,m3)),
                             fmaxf(fmaxf(m4,m5), fmaxf(m6,m7)));
                gw = __reduce_max_sync(0xffffffffu, __float_as_uint(tmax));
                wthresh = __uint_as_float(gw) * 1.0001f;
            }
            if (lane == 0) rv[buf*NWARP + wid] = gw;
            __syncthreads();

            // global value max from 16 warp partials
            unsigned pv = (lane < NWARP) ? rv[buf*NWARP + lane] : 0u;
            unsigned g2 = __reduce_max_sync(0xffffffffu, pv);

            if (tid == 0) scombo[buf ^ 1] = 0x7FFFFFFF;   // reset for next iter
            // rare path: winner thread(s) publish exact (orig<<13|pos) combo
            if (__float_as_uint(tmax) == g2) {
                int best = 0x7FFFFFFF;
                #pragma unroll
                for (int j = 0; j < PPT; j++) {
                    if (__float_as_uint(dd[j]) == g2) {
                        int cmb = (sorig[i0+j] << 13) | (i0 + j);
                        best = min(best, cmb);
                    }
                }
                atomicMin(&scombo[buf], best);
            }
            __syncthreads();
            cur = scombo[buf] & 0x1FFF;
        }
        return;
    }

    // ==================== worker path (512 threads) ====================
    int w = blockIdx.x - BB;       // 0..145
    int b = w & 1;
    int ws = w >> 1;               // 0..72

    float* sx = sm;
    float* sy = sm + NN;
    float* sz = sm + 2*NN;
    float* gT = sm + 3*NN;                 // [CIN][KNN]
    float* hS = gT + CIN*KNN;              // [C1][KNN]
    int*   sid = (int*)(hS + C1*KNN);      // [KNN]
    int*   soi = sid + KNN;

    const float* base = xyz + b*NN*3;
    for (int i = tid; i < NN; i += NT) {
        sx[i] = base[i*3+0]; sy[i] = base[i*3+1]; sz[i] = base[i*3+2];
    }
    // redundant weight transposes (identical concurrent writes are benign)
    for (int e = tid; e < C1*CIN; e += NT)
        g_W1t[(e % CIN)*C1 + (e / CIN)] = W1[e];
    for (int e = tid; e < C2*C1; e += NT)
        g_W2t[(e % C1)*C2 + (e / C1)] = W2[e];
    __syncthreads();

    for (int m = ws; m < MM; m += WPB) {
        // ---- wait for ticket ----
        if (tid == 0) {
            int v;
            while ((v = ((volatile int*)g_sel)[b*MM + m]) == 0) __nanosleep(64);
            *soi = v - 1;
        }
        __syncthreads();
        int oi = *soi;
        float cx = sx[oi], cy = sy[oi], cz = sz[oi];

        // ---- ball query: warp 0, first-K in index order ----
        if (tid < 32) {
            int cnt = 0; int first = -1;
            for (int c = 0; c < NN/32; c++) {
                int i = c*32 + lane;
                float dx = sx[i]-cx, dy = sy[i]-cy, dz = sz[i]-cz;
                float d2 = __fadd_rn(__fadd_rn(__fmul_rn(dx,dx), __fmul_rn(dy,dy)),
                                     __fmul_rn(dz,dz));
                bool in = d2 < 0.01f;
                unsigned msk = __ballot_sync(0xffffffffu, in);
                if (first < 0 && msk) first = c*32 + (__ffs(msk) - 1);
                if (in) {
                    int slot = cnt + __popc(msk & ((1u << lane) - 1u));
                    if (slot < KNN) sid[slot] = i;
                }
                cnt += __popc(msk);
                if (cnt >= KNN) break;
            }
            for (int s2 = cnt + lane; s2 < KNN; s2 += 32) sid[s2] = first;
        }
        __syncthreads();

        // ---- gather group matrix gT[c][k] ----
        for (int e = tid; e < CIN*KNN; e += NT) {
            int c = e >> 5, k = e & 31;
            int id = sid[k];
            float v;
            if      (c == 0) v = sx[id] - cx;
            else if (c == 1) v = sy[id] - cy;
            else if (c == 2) v = sz[id] - cz;
            else             v = x[(b*C0 + (c - 3))*NN + id];
            gT[c*KNN + k] = v;
        }
        __syncthreads();

        // ---- layer 1: thread = (o in [0,128), quarter of k -> 8 accs) ----
        {
            int o = tid >> 2, k0 = (tid & 3) * 8;
            float a0 = b1[o], a1=a0,a2=a0,a3=a0,a4=a0,a5=a0,a6=a0,a7=a0;
            for (int c = 0; c < CIN; c++) {
                float wv = g_W1t[c*C1 + o];
                float4 g0 = *(const float4*)&gT[c*KNN + k0];
                float4 g1 = *(const float4*)&gT[c*KNN + k0 + 4];
                a0 = fmaf(wv, g0.x, a0); a1 = fmaf(wv, g0.y, a1);
                a2 = fmaf(wv, g0.z, a2); a3 = fmaf(wv, g0.w, a3);
                a4 = fmaf(wv, g1.x, a4); a5 = fmaf(wv, g1.y, a5);
                a6 = fmaf(wv, g1.z, a6); a7 = fmaf(wv, g1.w, a7);
            }
            *(float4*)&hS[o*KNN + k0] =
                make_float4(fmaxf(a0,0.f), fmaxf(a1,0.f), fmaxf(a2,0.f), fmaxf(a3,0.f));
            *(float4*)&hS[o*KNN + k0 + 4] =
                make_float4(fmaxf(a4,0.f), fmaxf(a5,0.f), fmaxf(a6,0.f), fmaxf(a7,0.f));
        }
        __syncthreads();

        // ---- layer 2: thread = (o in [0,256), half of k -> 16 accs) ----
        {
            int o = tid >> 1, g = tid & 1, k0 = g * 16;
            float acc[16];
            #pragma unroll
            for (int q = 0; q < 16; q++) acc[q] = 0.f;
            #pragma unroll 4
            for (int c = 0; c < C1; c++) {
                float wv = g_W2t[c*C2 + o];
                const float4* hp = (const float4*)&hS[c*KNN + k0];
                #pragma unroll
                for (int q = 0; q < 4; q++) {
                    float4 hv = hp[q];
                    acc[q*4+0] = fmaf(wv, hv.x, acc[q*4+0]);
                    acc[q*4+1] = fmaf(wv, hv.y, acc[q*4+1]);
                    acc[q*4+2] = fmaf(wv, hv.z, acc[q*4+2]);
                    acc[q*4+3] = fmaf(wv, hv.w, acc[q*4+3]);
                }
            }
            float pm = acc[0];
            #pragma unroll
            for (int q = 1; q < 16; q++) pm = fmaxf(pm, acc[q]);
            pm = fmaxf(pm, __shfl_xor_sync(0xffffffffu, pm, 1));
            if (g == 0) g_p[(b*MM + m)*C2 + o] = pm + b2[o];
        }
        __syncthreads();
    }
}

// ---------------- BN stats: one block per channel ----------------
__global__ void __launch_bounds__(256)
bn_stats_kernel(const float* __restrict__ gamma, const float* __restrict__ beta) {
    int o = blockIdx.x, t = threadIdx.x;
    float s = 0.f, s2 = 0.f;
    for (int i = t; i < BB*MM; i += 256) {
        float v = g_p[i*C2 + o];
        s += v; s2 = fmaf(v, v, s2);
    }
    __shared__ float ss[32], ssq[32];
    #pragma unroll
    for (int off = 16; off > 0; off >>= 1) {
        s  += __shfl_down_sync(0xffffffffu, s, off);
        s2 += __shfl_down_sync(0xffffffffu, s2, off);
    }
    if ((t & 31) == 0) { ss[t>>5] = s; ssq[t>>5] = s2; }
    __syncthreads();
    if (t < 32) {
        float a  = (t < 8) ? ss[t]  : 0.f;
        float aq = (t < 8) ? ssq[t] : 0.f;
        #pragma unroll
        for (int off = 4; off > 0; off >>= 1) {
            a  += __shfl_down_sync(0xffffffffu, a, off);
            aq += __shfl_down_sync(0xffffffffu, aq, off);
        }
        if (t == 0) {
            const float inv_n = 1.0f / (BB*MM);
            float mean = a * inv_n;
            float var  = fmaxf(aq * inv_n - mean*mean, 0.f);
            float rstd = rsqrtf(var + 1e-5f);
            float sc = rstd * gamma[o];
            g_scale[o] = sc;
            g_shift[o] = beta[o] - mean * sc;
        }
    }
}

// ---------------- normalize + transpose to (B, C2, M) ----------------
__global__ void __launch_bounds__(256)
norm_kernel(float* __restrict__ out) {
    int b = blockIdx.x >> 8, o = blockIdx.x & 255, t = threadIdx.x;
    float sc = g_scale[o], sh = g_shift[o];
    float* ob = out + OUT_OFS + (b*C2 + o)*MM;
    const float* pb = g_p + b*MM*C2 + o;
    for (int mm = t; mm < MM; mm += 256)
        ob[mm] = fmaf(pb[mm*C2], sc, sh);
}

// ---------------- launch ----------------
extern "C" void kernel_launch(void* const* d_in, const int* in_sizes, int n_in,
                              void* d_out, int out_size) {
    const float* xyz   = (const float*)d_in[0];
    const float* x     = (const float*)d_in[1];
    const float* W1    = (const float*)d_in[2];
    const float* b1    = (const float*)d_in[3];
    const float* W2    = (const float*)d_in[4];
    const float* b2    = (const float*)d_in[5];
    const float* gamma = (const float*)d_in[6];
    const float* beta  = (const float*)d_in[7];
    float* out = (float*)d_out;

    size_t smem = (size_t)FPS_SMEM_FLOATS * 4;
    cudaFuncSetAttribute(fused_kernel, cudaFuncAttributeMaxDynamicSharedMemorySize, (int)smem);

    fused_kernel<<<BB + NWORK, NT, smem>>>(xyz, x, W1, b1, W2, b2, out);
    bn_stats_kernel<<<C2, 256>>>(gamma, beta);
    norm_kernel<<<BB*C2, 256>>>(out);
}